// round 1
// baseline (speedup 1.0000x reference)
#include <cuda_runtime.h>
#include <cstdint>

#define B_  512
#define T_  2048
#define D_  64
#define H_  66
#define G4  264      // 4*H
#define ROWS_PB 64   // rows per block in projection kernel

// ---- scratch (static device arrays: no allocation allowed) ----
__device__ float g_xproj[(size_t)B_ * T_ * G4];   // [B*T, 4H] input projection (+bias)
__device__ float g_hT[B_ * H_];                   // final hidden state
__device__ float g_bn_a[H_];                      // gamma * rsqrt(var+eps)
__device__ float g_bn_b[H_];                      // beta - mean * a

// ---- packed f32x2 helpers (sm_103a FFMA2 path) ----
#define FMA2(d, a, b, c) asm("fma.rn.f32x2 %0, %1, %2, %3;" : "=l"(d) : "l"(a), "l"(b), "l"(c))
#define ADD2(d, a, b)    asm("add.rn.f32x2 %0, %1, %2;"     : "=l"(d) : "l"(a), "l"(b))
#define PACK2(d, lo, hi) asm("mov.b64 %0, {%1, %2};"        : "=l"(d) : "f"(lo), "f"(hi))
#define UNPACK2(lo, hi, s) asm("mov.b64 {%0, %1}, %2;"      : "=f"(lo), "=f"(hi) : "l"(s))

// ============================================================
// Kernel 1: x_proj[row, g] = dot(x[row,:64], W_ih[g,:64]) + b_ih[g] + b_hh[g]
// One thread per gate column g; W row held in 32 packed f32x2 registers.
// ============================================================
__global__ __launch_bounds__(G4, 2) void proj_kernel(
    const float* __restrict__ x, const float* __restrict__ W_ih,
    const float* __restrict__ b_ih, const float* __restrict__ b_hh)
{
    __shared__ float xs[ROWS_PB * D_];
    const int g = threadIdx.x;
    const long long row0 = (long long)blockIdx.x * ROWS_PB;

    // W_ih row g -> packed registers (row is 256B aligned -> ulonglong2 loads OK)
    unsigned long long w2[D_ / 2];
    {
        const ulonglong2* wp = (const ulonglong2*)(W_ih + (size_t)g * D_);
        #pragma unroll
        for (int i = 0; i < D_ / 4; i++) { ulonglong2 v = wp[i]; w2[2*i] = v.x; w2[2*i+1] = v.y; }
    }
    const float bias = b_ih[g] + b_hh[g];

    // cooperative load of 64 x-rows into smem
    const float4* xg = (const float4*)(x + row0 * D_);
    float4* xs4 = (float4*)xs;
    for (int i = g; i < ROWS_PB * D_ / 4; i += G4) xs4[i] = xg[i];
    __syncthreads();

    float* outp = g_xproj + row0 * G4 + g;
    #pragma unroll 2
    for (int r = 0; r < ROWS_PB; r++) {
        const ulonglong2* hp = (const ulonglong2*)(xs + r * D_);   // broadcast reads
        unsigned long long a0 = 0ull, a1 = 0ull;
        #pragma unroll
        for (int k = 0; k < D_ / 4; k++) {
            ulonglong2 hv = hp[k];
            FMA2(a0, w2[2*k],     hv.x, a0);
            FMA2(a1, w2[2*k + 1], hv.y, a1);
        }
        ADD2(a0, a0, a1);
        float lo, hi; UNPACK2(lo, hi, a0);
        outp[(long long)r * G4] = lo + hi + bias;
    }
}

// ============================================================
// Kernel 2: recurrence. One block per batch element, 264 threads.
// Thread g computes gate pre-activation g via 66-wide dot (W_hh row in regs,
// h broadcast from smem as packed pairs). Threads 0..65 update (c,h).
// ============================================================
__global__ __launch_bounds__(G4, 2) void lstm_kernel(const float* __restrict__ W_hh)
{
    __shared__ float sh_h[H_ + 2];   // padded to 68 for LDS.128
    __shared__ float sh_g[G4];

    const int g = threadIdx.x;
    const int b = blockIdx.x;

    // W_hh row g (66 floats, only 8B-aligned) -> pack once into 34 f32x2 regs
    unsigned long long w2[34];
    {
        const float* wr = W_hh + (size_t)g * H_;
        #pragma unroll
        for (int i = 0; i < 33; i++) PACK2(w2[i], wr[2*i], wr[2*i + 1]);
        PACK2(w2[33], 0.f, 0.f);     // covers padded h[66..67]
    }

    if (g < H_ + 2) sh_h[g] = 0.f;
    float c = 0.f, h = 0.f;
    const bool tanh_gate = (g >= 2 * H_) && (g < 3 * H_);

    const float* xp_base = g_xproj + (long long)b * T_ * G4 + g;
    float xp = xp_base[0];
    __syncthreads();

    for (int t = 0; t < T_; t++) {
        // prefetch next timestep's x_proj (fully hidden behind dot + 2 barriers)
        const int tn = (t + 1 < T_) ? (t + 1) : t;
        const float xp_next = xp_base[(long long)tn * G4];

        // gate pre-activation: dot(W_hh[g,:], h) + x_proj
        const ulonglong2* hp = (const ulonglong2*)sh_h;
        unsigned long long a0 = 0ull, a1 = 0ull;
        #pragma unroll
        for (int k = 0; k < 17; k++) {
            ulonglong2 hv = hp[k];
            FMA2(a0, w2[2*k],     hv.x, a0);
            FMA2(a1, w2[2*k + 1], hv.y, a1);
        }
        ADD2(a0, a0, a1);
        float lo, hi; UNPACK2(lo, hi, a0);
        const float pre = lo + hi + xp;

        // activation: sigmoid for i,f,o; tanh (=2*sigmoid(2x)-1, overflow-safe) for g
        const float arg = tanh_gate ? (-2.f * pre) : (-pre);
        const float e = __expf(arg);
        const float s = __fdividef(1.f, 1.f + e);
        sh_g[g] = tanh_gate ? (2.f * s - 1.f) : s;
        __syncthreads();

        if (g < H_) {
            const float i_ = sh_g[g];
            const float f_ = sh_g[H_ + g];
            const float gg = sh_g[2 * H_ + g];
            const float o_ = sh_g[3 * H_ + g];
            c = f_ * c + i_ * gg;
            const float e2 = __expf(-2.f * c);
            const float tc = __fdividef(2.f, 1.f + e2) - 1.f;
            h = o_ * tc;
            sh_h[g] = h;
        }
        __syncthreads();
        xp = xp_next;
    }
    if (g < H_) g_hT[b * H_ + g] = h;
}

// ============================================================
// Kernel 3: batch-norm statistics (training-mode batch stats, biased var)
// One block per feature j; 512 threads reduce over batch.
// ============================================================
__global__ void bn_stats_kernel(const float* __restrict__ gamma, const float* __restrict__ beta)
{
    const int j = blockIdx.x;
    const int t = threadIdx.x;
    float v = g_hT[t * H_ + j];
    float s = v, q = v * v;
    #pragma unroll
    for (int o = 16; o > 0; o >>= 1) {
        s += __shfl_down_sync(0xffffffffu, s, o);
        q += __shfl_down_sync(0xffffffffu, q, o);
    }
    __shared__ float ws[16], wq[16];
    if ((t & 31) == 0) { ws[t >> 5] = s; wq[t >> 5] = q; }
    __syncthreads();
    if (t < 16) {
        s = ws[t]; q = wq[t];
        #pragma unroll
        for (int o = 8; o > 0; o >>= 1) {
            s += __shfl_down_sync(0x0000ffffu, s, o);
            q += __shfl_down_sync(0x0000ffffu, q, o);
        }
        if (t == 0) {
            const float mean = s * (1.f / B_);
            const float var  = q * (1.f / B_) - mean * mean;
            const float a = gamma[j] * rsqrtf(var + 1e-5f);
            g_bn_a[j] = a;
            g_bn_b[j] = beta[j] - mean * a;
        }
    }
}

// ============================================================
// Kernel 4: logits[b] = fc_b + sum_j (a[j]*h[b,j] + b2[j]) * fc_w[j]
// ============================================================
__global__ void head_kernel(const float* __restrict__ fc_w, const float* __restrict__ fc_b,
                            float* __restrict__ out)
{
    const int b = blockIdx.x * blockDim.x + threadIdx.x;
    if (b >= B_) return;
    float acc = fc_b[0];
    #pragma unroll
    for (int j = 0; j < H_; j++)
        acc += (g_bn_a[j] * g_hT[b * H_ + j] + g_bn_b[j]) * fc_w[j];
    out[b] = acc;
}

// ============================================================
extern "C" void kernel_launch(void* const* d_in, const int* in_sizes, int n_in,
                              void* d_out, int out_size)
{
    const float* x     = (const float*)d_in[0];
    const float* W_ih  = (const float*)d_in[1];
    const float* W_hh  = (const float*)d_in[2];
    const float* b_ih  = (const float*)d_in[3];
    const float* b_hh  = (const float*)d_in[4];
    const float* gamma = (const float*)d_in[5];
    const float* beta  = (const float*)d_in[6];
    const float* fc_w  = (const float*)d_in[7];
    const float* fc_b  = (const float*)d_in[8];
    float* out = (float*)d_out;

    proj_kernel<<<(B_ * T_) / ROWS_PB, G4>>>(x, W_ih, b_ih, b_hh);
    lstm_kernel<<<B_, G4>>>(W_hh);
    bn_stats_kernel<<<H_, B_>>>(gamma, beta);
    head_kernel<<<2, 256>>>(fc_w, fc_b, out);
}